// round 1
// baseline (speedup 1.0000x reference)
#include <cuda_runtime.h>
#include <cuda_bf16.h>

// ---------------------------------------------------------------------------
// VQC: 4 qubits, 3 layers, BATCH=524288.
// Decomposition:
//   state_after_inputs s = product state from RY(x_i) on |0>  (real, 16 values)
//   layers = fixed 16x16 complex unitary U(weights)            (batch-invariant)
//   out_w  = sum_k sign_{w,k} * |(U s)_k|^2                    (signs compile-time)
// Kernel 1 builds U (16 threads, one column each).
// Kernel 2 applies U per element using packed fma.rn.f32x2 (lanes = rows k,k+1).
// ---------------------------------------------------------------------------

#define NQ 4
#define DIM 16

// g_U[kp*16 + j] = (re[2kp][j], re[2kp+1][j], im[2kp][j], im[2kp+1][j])
__device__ float4 g_U[128];

// ---------------- packed f32x2 helpers (PTX-only on Blackwell) -------------
__device__ __forceinline__ unsigned long long pack2(float lo, float hi) {
    unsigned long long r;
    asm("mov.b64 %0, {%1, %2};" : "=l"(r) : "f"(lo), "f"(hi));
    return r;
}
__device__ __forceinline__ void unpack2(unsigned long long v, float& lo, float& hi) {
    asm("mov.b64 {%0, %1}, %2;" : "=f"(lo), "=f"(hi) : "l"(v));
}
__device__ __forceinline__ unsigned long long fma2(unsigned long long a,
                                                   unsigned long long b,
                                                   unsigned long long c) {
    unsigned long long d;
    asm("fma.rn.f32x2 %0, %1, %2, %3;" : "=l"(d) : "l"(a), "l"(b), "l"(c));
    return d;
}
__device__ __forceinline__ unsigned long long mul2(unsigned long long a,
                                                   unsigned long long b) {
    unsigned long long d;
    asm("mul.rn.f32x2 %0, %1, %2;" : "=l"(d) : "l"(a), "l"(b));
    return d;
}
__device__ __forceinline__ unsigned long long add2(unsigned long long a,
                                                   unsigned long long b) {
    unsigned long long d;
    asm("add.rn.f32x2 %0, %1, %2;" : "=l"(d) : "l"(a), "l"(b));
    return d;
}
__device__ __forceinline__ unsigned long long sub2(unsigned long long a,
                                                   unsigned long long b) {
    unsigned long long d;
    asm("sub.rn.f32x2 %0, %1, %2;" : "=l"(d) : "l"(a), "l"(b));
    return d;
}

// ---------------- Kernel 1: build the layer unitary U ----------------------
// Thread j propagates basis state e_j through 3 layers:
//   per layer: CNOT(i, (i+1)%4) for i=0..3, then RY(w[l,i,0]); RZ(w[l,i,1]) per wire.
// Qubit w lives at bit (3-w) of the state index.
__global__ void build_u_kernel(const float* __restrict__ w) {
    const int j = threadIdx.x;
    if (j >= DIM) return;

    float sr[DIM], si[DIM];
#pragma unroll
    for (int i = 0; i < DIM; ++i) { sr[i] = (i == j) ? 1.0f : 0.0f; si[i] = 0.0f; }

#pragma unroll
    for (int layer = 0; layer < 3; ++layer) {
        // CNOT ring (gather: new[idx] = old[idx ^ (ctrlbit(idx) << tbit)])
#pragma unroll
        for (int g = 0; g < 4; ++g) {
            const int cb = 3 - g;
            const int tb = 3 - ((g + 1) & 3);
            float tr[DIM], ti[DIM];
#pragma unroll
            for (int idx = 0; idx < DIM; ++idx) {
                const int src = idx ^ (((idx >> cb) & 1) << tb);
                tr[idx] = sr[src]; ti[idx] = si[src];
            }
#pragma unroll
            for (int idx = 0; idx < DIM; ++idx) { sr[idx] = tr[idx]; si[idx] = ti[idx]; }
        }
        // RY then RZ per wire
#pragma unroll
        for (int g = 0; g < 4; ++g) {
            const float hy = 0.5f * w[(layer * 4 + g) * 2 + 0];
            const float hz = 0.5f * w[(layer * 4 + g) * 2 + 1];
            float cy, sy, cz, sz;
            __sincosf(hy, &sy, &cy);
            __sincosf(hz, &sz, &cz);
            const int bit = 3 - g;
            const int mask = 1 << bit;
#pragma unroll
            for (int idx = 0; idx < DIM; ++idx) {
                if (idx & mask) continue;
                const int i0 = idx, i1 = idx | mask;
                const float a0r = sr[i0], a0i = si[i0];
                const float a1r = sr[i1], a1i = si[i1];
                // RY
                const float b0r = cy * a0r - sy * a1r, b0i = cy * a0i - sy * a1i;
                const float b1r = sy * a0r + cy * a1r, b1i = sy * a0i + cy * a1i;
                // RZ: amp(bit=0) *= (cz - i sz); amp(bit=1) *= (cz + i sz)
                sr[i0] = cz * b0r + sz * b0i;  si[i0] = cz * b0i - sz * b0r;
                sr[i1] = cz * b1r - sz * b1i;  si[i1] = cz * b1i + sz * b1r;
            }
        }
    }

#pragma unroll
    for (int kp = 0; kp < 8; ++kp)
        g_U[kp * 16 + j] = make_float4(sr[2 * kp], sr[2 * kp + 1],
                                       si[2 * kp], si[2 * kp + 1]);
}

// ---------------- Kernel 2: batched apply + measure -------------------------
#define TPB 256
#define EPT 2   // elements per thread

__global__ __launch_bounds__(TPB, 2)
void vqc_apply_kernel(const float* __restrict__ x, float* __restrict__ out, int B) {
    // smem: [kp*16+j] -> { pack(re_k, re_k+1), pack(im_k, im_k+1) }
    __shared__ float4 sU[128];
    const int t = threadIdx.x;
    if (t < 128) sU[t] = g_U[t];
    __syncthreads();

    const int base = blockIdx.x * (TPB * EPT) + t;

    unsigned long long pp[EPT][16];   // pp[e][j] = (p_j, p_j)
    bool valid[EPT];

#pragma unroll
    for (int e = 0; e < EPT; ++e) {
        const int b = base + e * TPB;
        valid[e] = (b < B);
        float4 xv = valid[e] ? reinterpret_cast<const float4*>(x)[b]
                             : make_float4(0.f, 0.f, 0.f, 0.f);
        float c0, s0, c1, s1, c2, s2, c3, s3;
        __sincosf(0.5f * xv.x, &s0, &c0);
        __sincosf(0.5f * xv.y, &s1, &c1);
        __sincosf(0.5f * xv.z, &s2, &c2);
        __sincosf(0.5f * xv.w, &s3, &c3);
        // product-state amplitudes: idx = b0*8 + b1*4 + b2*2 + b3 (wire w -> bit 3-w)
        const float m0 = c0 * c1, m1 = c0 * s1, m2 = s0 * c1, m3 = s0 * s1;
        const float n0 = c2 * c3, n1 = c2 * s3, n2 = s2 * c3, n3 = s2 * s3;
        const float m[4] = {m0, m1, m2, m3};
        const float n[4] = {n0, n1, n2, n3};
#pragma unroll
        for (int a = 0; a < 4; ++a) {
            const unsigned long long mm = pack2(m[a], m[a]);
#pragma unroll
            for (int c = 0; c < 4; ++c) {
                const unsigned long long nn = pack2(n[c], n[c]);
                pp[e][a * 4 + c] = mul2(mm, nn);
            }
        }
    }

    // packed-zero == 0ull
    unsigned long long z0[EPT], z1[EPT], z2[EPT], zd[EPT];
#pragma unroll
    for (int e = 0; e < EPT; ++e) { z0[e] = 0ull; z1[e] = 0ull; z2[e] = 0ull; zd[e] = 0ull; }

#pragma unroll
    for (int kp = 0; kp < 8; ++kp) {
        unsigned long long aR[EPT], aI[EPT];
#pragma unroll
        for (int e = 0; e < EPT; ++e) { aR[e] = 0ull; aI[e] = 0ull; }

#pragma unroll
        for (int j = 0; j < 16; ++j) {
            // one broadcast LDS.128: lanes already packed as (re_k,re_k+1),(im_k,im_k+1)
            const ulonglong2 u = reinterpret_cast<const ulonglong2*>(sU)[kp * 16 + j];
#pragma unroll
            for (int e = 0; e < EPT; ++e) {
                aR[e] = fma2(u.x, pp[e][j], aR[e]);
                aI[e] = fma2(u.y, pp[e][j], aI[e]);
            }
        }

#pragma unroll
        for (int e = 0; e < EPT; ++e) {
            // (|amp_k|^2, |amp_{k+1}|^2)
            const unsigned long long pr = fma2(aI[e], aI[e], mul2(aR[e], aR[e]));
            // signs: z_w uses bit (3-w) of k; lanes k=2kp, 2kp+1 share bits 3..1
            if ((kp >> 2) & 1) z0[e] = sub2(z0[e], pr); else z0[e] = add2(z0[e], pr);
            if ((kp >> 1) & 1) z1[e] = sub2(z1[e], pr); else z1[e] = add2(z1[e], pr);
            if (kp & 1)        z2[e] = sub2(z2[e], pr); else z2[e] = add2(z2[e], pr);
            zd[e] = add2(zd[e], pr);   // qubit 3: lane0 '+', lane1 '-'
        }
    }

#pragma unroll
    for (int e = 0; e < EPT; ++e) {
        if (!valid[e]) continue;
        float a, b2;
        unpack2(z0[e], a, b2); const float r0 = a + b2;
        unpack2(z1[e], a, b2); const float r1 = a + b2;
        unpack2(z2[e], a, b2); const float r2 = a + b2;
        unpack2(zd[e], a, b2); const float r3 = a - b2;
        reinterpret_cast<float4*>(out)[base + e * TPB] = make_float4(r0, r1, r2, r3);
    }
}

// ---------------------------------------------------------------------------
extern "C" void kernel_launch(void* const* d_in, const int* in_sizes, int n_in,
                              void* d_out, int out_size) {
    // x: B*4 floats, weights: 24 floats (order-robust)
    int ix = 0, iw = 1;
    if (n_in >= 2 && in_sizes[0] <= in_sizes[1]) { ix = 1; iw = 0; }
    const float* x = (const float*)d_in[ix];
    const float* w = (const float*)d_in[iw];
    float* out = (float*)d_out;
    const int B = in_sizes[ix] / 4;

    build_u_kernel<<<1, DIM>>>(w);
    const int per_block = TPB * EPT;
    const int grid = (B + per_block - 1) / per_block;
    vqc_apply_kernel<<<grid, TPB>>>(x, out, B);
}